// round 11
// baseline (speedup 1.0000x reference)
#include <cuda_runtime.h>
#include <cuda_fp16.h>
#include <cstdint>

#define B_  8
#define C_  64
#define HW_ 4096

// ---------------- scratch globals (no allocation) ----------------
__device__ __half g_q[(size_t)B_*HW_*C_];   // [b][n][c]  (scaled by log2e/8)
__device__ __half g_k[(size_t)B_*HW_*C_];   // [b][n][c]
__device__ __half g_v[(size_t)B_*HW_*C_];   // [b][n][c]

__device__ __forceinline__ uint32_t smem_u32(const void* p) {
    uint32_t a;
    asm("{ .reg .u64 t; cvta.to.shared.u64 t, %1; cvt.u32.u64 %0, t; }" : "=r"(a) : "l"(p));
    return a;
}

// f32-accum HMMA (epilogue-free path kept for reference / not used in loop)
#define MMA16816(c, a, b0, b1)                                                  \
    asm volatile("mma.sync.aligned.m16n8k16.row.col.f32.f16.f16.f32 "           \
        "{%0,%1,%2,%3}, {%4,%5,%6,%7}, {%8,%9}, {%0,%1,%2,%3};"                 \
        : "+f"((c)[0]), "+f"((c)[1]), "+f"((c)[2]), "+f"((c)[3])                \
        : "r"((a)[0]), "r"((a)[1]), "r"((a)[2]), "r"((a)[3]), "r"(b0), "r"(b1))

// f16-accum HMMA (D,C = 2x f16x2 regs) — 2x rate on consumer-lineage parts
#define MMA16816H(d0, d1, a, b0, b1)                                            \
    asm volatile("mma.sync.aligned.m16n8k16.row.col.f16.f16.f16.f16 "           \
        "{%0,%1}, {%2,%3,%4,%5}, {%6,%7}, {%0,%1};"                              \
        : "+r"(d0), "+r"(d1)                                                     \
        : "r"((a)[0]), "r"((a)[1]), "r"((a)[2]), "r"((a)[3]), "r"(b0), "r"(b1))

#define LDSM4(r, a)                                                             \
    asm volatile("ldmatrix.sync.aligned.m8n8.x4.shared.b16 {%0,%1,%2,%3}, [%4];"\
        : "=r"((r)[0]), "=r"((r)[1]), "=r"((r)[2]), "=r"((r)[3]) : "r"(a))

#define LDSM4T(r, a)                                                            \
    asm volatile("ldmatrix.sync.aligned.m8n8.x4.trans.shared.b16 {%0,%1,%2,%3}, [%4];"\
        : "=r"((r)[0]), "=r"((r)[1]), "=r"((r)[2]), "=r"((r)[3]) : "r"(a))

#define CP16(dst, src) asm volatile("cp.async.cg.shared.global [%0], [%1], 16;" :: "r"(dst), "l"(src))
#define CP_COMMIT()    asm volatile("cp.async.commit_group;" ::: "memory")
#define CP_WAIT1()     asm volatile("cp.async.wait_group 1;" ::: "memory")
#define CP_WAIT0()     asm volatile("cp.async.wait_group 0;" ::: "memory")

// hardware exp2 (MUFU.EX2 f32)
__device__ __forceinline__ float fexp2(float x) {
    float y;
    asm("ex2.approx.f32 %0, %1;" : "=f"(y) : "f"(x));
    return y;
}

// ---------------------------------------------------------------------------
// QKV projection (unchanged, proven).
// ---------------------------------------------------------------------------
#define QKV_SMEM (64*68*4 + 3*64*65*4 + 3*64*4)

__global__ __launch_bounds__(256) void qkv_kernel(
    const float* __restrict__ x,
    const float* __restrict__ wq, const float* __restrict__ bq,
    const float* __restrict__ wk, const float* __restrict__ bk,
    const float* __restrict__ wv, const float* __restrict__ bv)
{
    extern __shared__ float smf[];
    float* xs  = smf;
    float* ws  = smf + 64*68;
    float* bsh = ws + 3*64*65;

    int tid = threadIdx.x;
    int b   = blockIdx.x >> 6;
    int n0  = (blockIdx.x & 63) << 6;
    const float* xb = x + (size_t)b*C_*HW_;

    #pragma unroll
    for (int k = 0; k < 16; k++) {
        int e = tid + 256*k; int c = e >> 6, i = e & 63;
        xs[c*68 + i] = xb[(size_t)c*HW_ + n0 + i];
    }
    #pragma unroll
    for (int k = 0; k < 16; k++) {
        int e = tid + 256*k;
        int c = e & 63, d = e >> 6;
        ws[c*65 + d]          = wq[e];
        ws[4160 + c*65 + d]   = wk[e];
        ws[8320 + c*65 + d]   = wv[e];
    }
    if (tid < 192) {
        bsh[tid] = (tid < 64) ? bq[tid] : (tid < 128) ? bk[tid - 64] : bv[tid - 128];
    }
    __syncthreads();

    int d = tid & 63, ib = (tid >> 6) << 4;
    float acc[3][16];
    #pragma unroll
    for (int k = 0; k < 16; k++) {
        acc[0][k] = bsh[d]; acc[1][k] = bsh[64 + d]; acc[2][k] = bsh[128 + d];
    }

    #pragma unroll 8
    for (int c = 0; c < 64; c++) {
        const float4* xr = (const float4*)(xs + c*68 + ib);
        float4 x0 = xr[0], x1 = xr[1], x2 = xr[2], x3 = xr[3];
        float xv[16] = {x0.x,x0.y,x0.z,x0.w, x1.x,x1.y,x1.z,x1.w,
                        x2.x,x2.y,x2.z,x2.w, x3.x,x3.y,x3.z,x3.w};
        float w0 = ws[c*65 + d], w1 = ws[4160 + c*65 + d], w2 = ws[8320 + c*65 + d];
        #pragma unroll
        for (int k = 0; k < 16; k++) {
            acc[0][k] = fmaf(xv[k], w0, acc[0][k]);
            acc[1][k] = fmaf(xv[k], w1, acc[1][k]);
            acc[2][k] = fmaf(xv[k], w2, acc[2][k]);
        }
    }

    const float scq = 0.18033688011112043f;   // log2(e)/8
    __half* qo = g_q + (size_t)b*HW_*C_;
    __half* ko = g_k + (size_t)b*HW_*C_;
    __half* vo = g_v + (size_t)b*HW_*C_;
    #pragma unroll
    for (int k = 0; k < 16; k++) {
        size_t o = (size_t)(n0 + ib + k)*C_ + d;
        qo[o] = __float2half_rn(acc[0][k]*scq);
        ko[o] = __float2half_rn(acc[1][k]);
        vo[o] = __float2half_rn(acc[2][k]);
    }
}

// ---------------------------------------------------------------------------
// Fused flash attention: f16-accumulator HMMA for S and O (fp32 master for O
// updated per key-tile), cp.async 3-stage K/V ring, f32 MUFU softmax,
// mix/ReLU/2x2-pool epilogue. One CTA per (b, 128-query tile).
// ---------------------------------------------------------------------------
#define PITCH 144
#define KVBUF 18432
#define SM_WMT (3*KVBUF)
#define ATTN_SMEM (3*KVBUF + 16384)

__device__ __forceinline__ void load_tile_async(
    uint32_t sb, int buf, const __half* kg, const __half* vg, int kn0, int tid)
{
    uint32_t dbase = sb + buf*KVBUF;
    const char* ksrc = (const char*)(kg + (size_t)kn0*C_);
    const char* vsrc = (const char*)(vg + (size_t)kn0*C_);
    #pragma unroll
    for (int k = 0; k < 2; k++) {
        int e = tid + 256*k;
        uint32_t doff = (e >> 3)*PITCH + (e & 7)*16;
        CP16(dbase + doff,        ksrc + e*16);
        CP16(dbase + 9216 + doff, vsrc + e*16);
    }
}

__global__ __launch_bounds__(256, 2) void attn_kernel(
    const float* __restrict__ wm, const float* __restrict__ bm,
    float* __restrict__ out)
{
    extern __shared__ __align__(16) char smem[];
    const uint32_t sb = smem_u32(smem);
    float* wmT = (float*)(smem + SM_WMT);

    int tid = threadIdx.x, wid = tid >> 5, lane = tid & 31;
    int b  = blockIdx.x >> 5;
    int it = blockIdx.x & 31;
    int n0 = it << 7;

    const __half* kg = g_k + (size_t)b*HW_*C_;
    const __half* vg = g_v + (size_t)b*HW_*C_;

    // ---- stage Q in buf0, load A fragments ----
    {
        const float4* q4 = (const float4*)(g_q + ((size_t)b*HW_ + n0)*C_);
        #pragma unroll
        for (int k = 0; k < 4; k++) {
            int e = tid + 256*k;
            *(float4*)(smem + (e >> 3)*PITCH + (e & 7)*16) = q4[e];
        }
    }
    __syncthreads();

    uint32_t qf[4][4];
    {
        int r  = 16*wid + (lane & 15);
        int cg = (lane >> 4) & 1;
        #pragma unroll
        for (int kt = 0; kt < 4; kt++)
            LDSM4(qf[kt], sb + r*PITCH + (kt*16 + cg*8)*2);
    }
    __syncthreads();

    // ---- prologue: async tiles 0,1; wmT while they fly ----
    load_tile_async(sb, 0, kg, vg, 0,  tid); CP_COMMIT();
    load_tile_async(sb, 1, kg, vg, 64, tid); CP_COMMIT();
    #pragma unroll
    for (int k = 0; k < 16; k++) {
        int e = tid + 256*k;
        wmT[(e & 63)*64 + (e >> 6)] = wm[e];
    }
    CP_WAIT1();
    __syncthreads();

    float oacc[8][4];
    #pragma unroll
    for (int j = 0; j < 8; j++)
        #pragma unroll
        for (int c = 0; c < 4; c++) oacc[j][c] = 0.f;
    float l0 = 0.f, l1 = 0.f;

    const uint32_t klane = ((lane & 7) + ((lane >> 4) & 1)*8)*PITCH + ((lane >> 3) & 1)*16;
    const uint32_t vlane = 9216 + ((lane & 7) + ((lane >> 3) & 1)*8)*PITCH + ((lane >> 4) & 1)*16;

    int cur = 0;
    for (int t = 0; t < 64; t++) {
        if (t < 62) {
            int nb = (cur == 0) ? 2 : cur - 1;
            load_tile_async(sb, nb, kg, vg, (t + 2) << 6, tid);
            CP_COMMIT();
        }

        const uint32_t base = sb + cur*KVBUF;

        // ---- S = Q K^T, f16 accumulators (sacc_h2[j] = {d0,d1 | d2,d3}) ----
        uint32_t sh[8][2];
        #pragma unroll
        for (int j = 0; j < 8; j++) { sh[j][0] = 0u; sh[j][1] = 0u; }

        const uint32_t kb = base + klane;
        #pragma unroll
        for (int ks = 0; ks < 4; ks++) {
            uint32_t kf0[4], kf1[4], kf2[4], kf3[4];
            LDSM4(kf0, kb + 0*(16*PITCH) + ks*32);
            LDSM4(kf1, kb + 1*(16*PITCH) + ks*32);
            LDSM4(kf2, kb + 2*(16*PITCH) + ks*32);
            LDSM4(kf3, kb + 3*(16*PITCH) + ks*32);
            MMA16816H(sh[0][0], sh[0][1], qf[ks], kf0[0], kf0[1]);
            MMA16816H(sh[1][0], sh[1][1], qf[ks], kf0[2], kf0[3]);
            MMA16816H(sh[2][0], sh[2][1], qf[ks], kf1[0], kf1[1]);
            MMA16816H(sh[3][0], sh[3][1], qf[ks], kf1[2], kf1[3]);
            MMA16816H(sh[4][0], sh[4][1], qf[ks], kf2[0], kf2[1]);
            MMA16816H(sh[5][0], sh[5][1], qf[ks], kf2[2], kf2[3]);
            MMA16816H(sh[6][0], sh[6][1], qf[ks], kf3[0], kf3[1]);
            MMA16816H(sh[7][0], sh[7][1], qf[ks], kf3[2], kf3[3]);
        }

        // ---- softmax (unpack f16 scores -> f32 exp2 -> repack P) ----
        uint32_t ph[4][4];
        #pragma unroll
        for (int ks = 0; ks < 4; ks++) {
            float2 a0 = __half22float2(*reinterpret_cast<__half2*>(&sh[2*ks][0]));
            float2 a1 = __half22float2(*reinterpret_cast<__half2*>(&sh[2*ks][1]));
            float2 b0 = __half22float2(*reinterpret_cast<__half2*>(&sh[2*ks+1][0]));
            float2 b1 = __half22float2(*reinterpret_cast<__half2*>(&sh[2*ks+1][1]));
            float p00 = fexp2(a0.x), p01 = fexp2(a0.y);
            float p02 = fexp2(a1.x), p03 = fexp2(a1.y);
            float p10 = fexp2(b0.x), p11 = fexp2(b0.y);
            float p12 = fexp2(b1.x), p13 = fexp2(b1.y);
            l0 += p00 + p01 + p10 + p11;
            l1 += p02 + p03 + p12 + p13;
            __half2 h0 = __floats2half2_rn(p00, p01);
            __half2 h1 = __floats2half2_rn(p02, p03);
            __half2 h2 = __floats2half2_rn(p10, p11);
            __half2 h3 = __floats2half2_rn(p12, p13);
            ph[ks][0] = *reinterpret_cast<uint32_t*>(&h0);
            ph[ks][1] = *reinterpret_cast<uint32_t*>(&h1);
            ph[ks][2] = *reinterpret_cast<uint32_t*>(&h2);
            ph[ks][3] = *reinterpret_cast<uint32_t*>(&h3);
        }

        // ---- O_tile = P V, f16 accumulators chained over ks; then -> master
        uint32_t oh[8][2];
        #pragma unroll
        for (int j = 0; j < 8; j++) { oh[j][0] = 0u; oh[j][1] = 0u; }

        const uint32_t vb = base + vlane;
        #pragma unroll
        for (int ks = 0; ks < 4; ks++) {
            #pragma unroll
            for (int cg = 0; cg < 4; cg++) {
                uint32_t vf[4];
                LDSM4T(vf, vb + ks*(16*PITCH) + cg*32);
                MMA16816H(oh[2*cg][0],   oh[2*cg][1],   ph[ks], vf[0], vf[1]);
                MMA16816H(oh[2*cg+1][0], oh[2*cg+1][1], ph[ks], vf[2], vf[3]);
            }
        }
        #pragma unroll
        for (int j = 0; j < 8; j++) {
            float2 lo = __half22float2(*reinterpret_cast<__half2*>(&oh[j][0]));
            float2 hi = __half22float2(*reinterpret_cast<__half2*>(&oh[j][1]));
            oacc[j][0] += lo.x; oacc[j][1] += lo.y;
            oacc[j][2] += hi.x; oacc[j][3] += hi.y;
        }

        if (t < 62) CP_WAIT1(); else CP_WAIT0();
        __syncthreads();
        cur = (cur == 2) ? 0 : cur + 1;
    }

    // ---- epilogue: normalize, mix GEMM + ReLU, 2x2 pool, store ----
    l0 += __shfl_xor_sync(0xffffffffu, l0, 1);
    l0 += __shfl_xor_sync(0xffffffffu, l0, 2);
    l1 += __shfl_xor_sync(0xffffffffu, l1, 1);
    l1 += __shfl_xor_sync(0xffffffffu, l1, 2);
    float inv0 = 1.f / l0, inv1 = 1.f / l1;

    float* sm_o = (float*)smem;     // o^T [64 c][132]
    {
        int r  = 16*wid + (lane >> 2);
        int c0 = 2*(lane & 3);
        #pragma unroll
        for (int j = 0; j < 8; j++) {
            sm_o[(8*j + c0    )*132 + r]     = oacc[j][0]*inv0;
            sm_o[(8*j + c0 + 1)*132 + r]     = oacc[j][1]*inv0;
            sm_o[(8*j + c0    )*132 + r + 8] = oacc[j][2]*inv1;
            sm_o[(8*j + c0 + 1)*132 + r + 8] = oacc[j][3]*inv1;
        }
    }
    __syncthreads();

    int tx = tid & 15, ty = tid >> 4;
    float4 bmv = ((const float4*)bm)[tx];
    float acc[8][4];
    #pragma unroll
    for (int ii = 0; ii < 8; ii++) {
        acc[ii][0] = bmv.x; acc[ii][1] = bmv.y; acc[ii][2] = bmv.z; acc[ii][3] = bmv.w;
    }
    #pragma unroll 8
    for (int c = 0; c < 64; c++) {
        float4 wv = *(const float4*)(wmT + c*64 + 4*tx);
        float4 o0 = *(const float4*)(sm_o + c*132 + 8*ty);
        float4 o1 = *(const float4*)(sm_o + c*132 + 8*ty + 4);
        float ov[8] = {o0.x,o0.y,o0.z,o0.w,o1.x,o1.y,o1.z,o1.w};
        #pragma unroll
        for (int ii = 0; ii < 8; ii++) {
            acc[ii][0] = fmaf(ov[ii], wv.x, acc[ii][0]);
            acc[ii][1] = fmaf(ov[ii], wv.y, acc[ii][1]);
            acc[ii][2] = fmaf(ov[ii], wv.z, acc[ii][2]);
            acc[ii][3] = fmaf(ov[ii], wv.w, acc[ii][3]);
        }
    }
    __syncthreads();

    float* sm_mx = (float*)smem;    // mixed [128 t][68]
    #pragma unroll
    for (int ii = 0; ii < 8; ii++) {
        float4 mv = make_float4(fmaxf(acc[ii][0], 0.f), fmaxf(acc[ii][1], 0.f),
                                fmaxf(acc[ii][2], 0.f), fmaxf(acc[ii][3], 0.f));
        *(float4*)(sm_mx + (8*ty + ii)*68 + 4*tx) = mv;
    }
    __syncthreads();

    float* ob = out + (size_t)b*C_*1024 + (size_t)it*32;
    #pragma unroll
    for (int k = 0; k < 8; k++) {
        int e = tid + 256*k;
        int j = e & 31, d = e >> 5;
        float v = sm_mx[(2*j)*68 + d] + sm_mx[(2*j + 1)*68 + d]
                + sm_mx[(64 + 2*j)*68 + d] + sm_mx[(64 + 2*j + 1)*68 + d];
        ob[(size_t)d*1024 + j] = 0.25f * v;
    }
}

extern "C" void kernel_launch(void* const* d_in, const int* in_sizes, int n_in,
                              void* d_out, int out_size)
{
    const float* x  = (const float*)d_in[0];
    const float* wq = (const float*)d_in[1];
    const float* bq = (const float*)d_in[2];
    const float* wk = (const float*)d_in[3];
    const float* bk = (const float*)d_in[4];
    const float* wv = (const float*)d_in[5];
    const float* bv = (const float*)d_in[6];
    const float* wm = (const float*)d_in[7];
    const float* bm = (const float*)d_in[8];
    float* out = (float*)d_out;

    cudaFuncSetAttribute(qkv_kernel,  cudaFuncAttributeMaxDynamicSharedMemorySize, QKV_SMEM);
    cudaFuncSetAttribute(attn_kernel, cudaFuncAttributeMaxDynamicSharedMemorySize, ATTN_SMEM);

    qkv_kernel<<<512, 256, QKV_SMEM>>>(x, wq, bq, wk, bk, wv, bv);
    attn_kernel<<<256, 256, ATTN_SMEM>>>(wm, bm, out);
}

// round 12
// speedup vs baseline: 1.0845x; 1.0845x over previous
#include <cuda_runtime.h>
#include <cuda_fp16.h>
#include <cstdint>

#define B_  8
#define C_  64
#define HW_ 4096

// ---------------- scratch globals (no allocation) ----------------
__device__ __half g_q[(size_t)B_*HW_*C_];   // [b][n][c]  (scaled by log2e/8)
__device__ __half g_k[(size_t)B_*HW_*C_];   // [b][n][c]
__device__ __half g_v[(size_t)B_*HW_*C_];   // [b][n][c]

__device__ __forceinline__ uint32_t smem_u32(const void* p) {
    uint32_t a;
    asm("{ .reg .u64 t; cvta.to.shared.u64 t, %1; cvt.u32.u64 %0, t; }" : "=r"(a) : "l"(p));
    return a;
}

#define MMA16816(c, a, b0, b1)                                                  \
    asm volatile("mma.sync.aligned.m16n8k16.row.col.f32.f16.f16.f32 "           \
        "{%0,%1,%2,%3}, {%4,%5,%6,%7}, {%8,%9}, {%0,%1,%2,%3};"                 \
        : "+f"((c)[0]), "+f"((c)[1]), "+f"((c)[2]), "+f"((c)[3])                \
        : "r"((a)[0]), "r"((a)[1]), "r"((a)[2]), "r"((a)[3]), "r"(b0), "r"(b1))

#define LDSM4(r, a)                                                             \
    asm volatile("ldmatrix.sync.aligned.m8n8.x4.shared.b16 {%0,%1,%2,%3}, [%4];"\
        : "=r"((r)[0]), "=r"((r)[1]), "=r"((r)[2]), "=r"((r)[3]) : "r"(a))

#define LDSM4T(r, a)                                                            \
    asm volatile("ldmatrix.sync.aligned.m8n8.x4.trans.shared.b16 {%0,%1,%2,%3}, [%4];"\
        : "=r"((r)[0]), "=r"((r)[1]), "=r"((r)[2]), "=r"((r)[3]) : "r"(a))

#define CP16(dst, src) asm volatile("cp.async.cg.shared.global [%0], [%1], 16;" :: "r"(dst), "l"(src))
#define CP_COMMIT()    asm volatile("cp.async.commit_group;" ::: "memory")
#define CP_WAIT1()     asm volatile("cp.async.wait_group 1;" ::: "memory")
#define CP_WAIT0()     asm volatile("cp.async.wait_group 0;" ::: "memory")

// hardware exp2 (MUFU.EX2 f32)
__device__ __forceinline__ float fexp2(float x) {
    float y;
    asm("ex2.approx.f32 %0, %1;" : "=f"(y) : "f"(x));
    return y;
}

// ---------------------------------------------------------------------------
// QKV projection (unchanged, proven).
// ---------------------------------------------------------------------------
#define QKV_SMEM (64*68*4 + 3*64*65*4 + 3*64*4)

__global__ __launch_bounds__(256) void qkv_kernel(
    const float* __restrict__ x,
    const float* __restrict__ wq, const float* __restrict__ bq,
    const float* __restrict__ wk, const float* __restrict__ bk,
    const float* __restrict__ wv, const float* __restrict__ bv)
{
    extern __shared__ float smf[];
    float* xs  = smf;
    float* ws  = smf + 64*68;
    float* bsh = ws + 3*64*65;

    int tid = threadIdx.x;
    int b   = blockIdx.x >> 6;
    int n0  = (blockIdx.x & 63) << 6;
    const float* xb = x + (size_t)b*C_*HW_;

    #pragma unroll
    for (int k = 0; k < 16; k++) {
        int e = tid + 256*k; int c = e >> 6, i = e & 63;
        xs[c*68 + i] = xb[(size_t)c*HW_ + n0 + i];
    }
    #pragma unroll
    for (int k = 0; k < 16; k++) {
        int e = tid + 256*k;
        int c = e & 63, d = e >> 6;
        ws[c*65 + d]          = wq[e];
        ws[4160 + c*65 + d]   = wk[e];
        ws[8320 + c*65 + d]   = wv[e];
    }
    if (tid < 192) {
        bsh[tid] = (tid < 64) ? bq[tid] : (tid < 128) ? bk[tid - 64] : bv[tid - 128];
    }
    __syncthreads();

    int d = tid & 63, ib = (tid >> 6) << 4;
    float acc[3][16];
    #pragma unroll
    for (int k = 0; k < 16; k++) {
        acc[0][k] = bsh[d]; acc[1][k] = bsh[64 + d]; acc[2][k] = bsh[128 + d];
    }

    #pragma unroll 8
    for (int c = 0; c < 64; c++) {
        const float4* xr = (const float4*)(xs + c*68 + ib);
        float4 x0 = xr[0], x1 = xr[1], x2 = xr[2], x3 = xr[3];
        float xv[16] = {x0.x,x0.y,x0.z,x0.w, x1.x,x1.y,x1.z,x1.w,
                        x2.x,x2.y,x2.z,x2.w, x3.x,x3.y,x3.z,x3.w};
        float w0 = ws[c*65 + d], w1 = ws[4160 + c*65 + d], w2 = ws[8320 + c*65 + d];
        #pragma unroll
        for (int k = 0; k < 16; k++) {
            acc[0][k] = fmaf(xv[k], w0, acc[0][k]);
            acc[1][k] = fmaf(xv[k], w1, acc[1][k]);
            acc[2][k] = fmaf(xv[k], w2, acc[2][k]);
        }
    }

    const float scq = 0.18033688011112043f;   // log2(e)/8
    __half* qo = g_q + (size_t)b*HW_*C_;
    __half* ko = g_k + (size_t)b*HW_*C_;
    __half* vo = g_v + (size_t)b*HW_*C_;
    #pragma unroll
    for (int k = 0; k < 16; k++) {
        size_t o = (size_t)(n0 + ib + k)*C_ + d;
        qo[o] = __float2half_rn(acc[0][k]*scq);
        ko[o] = __float2half_rn(acc[1][k]);
        vo[o] = __float2half_rn(acc[2][k]);
    }
}

// ---------------------------------------------------------------------------
// Fused flash attention: f32-accum HMMA, 128-key tiles processed as two
// 64-key halves between ONE cp.async wait + ONE barrier (3-stage 36KB ring),
// f32 MUFU softmax in log2 domain, mix/ReLU/2x2-pool epilogue (wmT loaded
// into reused smem at epilogue). One CTA per (b, 128-query tile).
// ---------------------------------------------------------------------------
#define PITCH 144                  // bytes per 64-half row (8 halves padding)
#define TILEB 36864                // one 128-key buffer: K 18432 + V 18432
#define ATTN_SMEM (3*TILEB)        // 110592

// async-load one 128-key K/V tile into ring buffer `buf`
__device__ __forceinline__ void load_tile_async(
    uint32_t sb, int buf, const __half* kg, const __half* vg, int kn0, int tid)
{
    uint32_t kd = sb + buf*TILEB;
    uint32_t vd = kd + 18432;
    const char* ksrc = (const char*)(kg + (size_t)kn0*C_);
    const char* vsrc = (const char*)(vg + (size_t)kn0*C_);
    #pragma unroll
    for (int k = 0; k < 4; k++) {
        int e = tid + 256*k;                    // 1024 16B-chunks per matrix
        uint32_t doff = (e >> 3)*PITCH + (e & 7)*16;
        CP16(kd + doff, ksrc + e*16);
        CP16(vd + doff, vsrc + e*16);
    }
}

__global__ __launch_bounds__(256, 2) void attn_kernel(
    const float* __restrict__ wm, const float* __restrict__ bm,
    float* __restrict__ out)
{
    extern __shared__ __align__(16) char smem[];
    const uint32_t sb = smem_u32(smem);

    int tid = threadIdx.x, wid = tid >> 5, lane = tid & 31;
    int b  = blockIdx.x >> 5;
    int it = blockIdx.x & 31;          // output row index
    int n0 = it << 7;

    const __half* kg = g_k + (size_t)b*HW_*C_;
    const __half* vg = g_v + (size_t)b*HW_*C_;

    // ---- stage Q in buf0 region, load A fragments ----
    {
        const float4* q4 = (const float4*)(g_q + ((size_t)b*HW_ + n0)*C_);
        #pragma unroll
        for (int k = 0; k < 4; k++) {
            int e = tid + 256*k;
            *(float4*)(smem + (e >> 3)*PITCH + (e & 7)*16) = q4[e];
        }
    }
    __syncthreads();

    uint32_t qf[4][4];
    {
        int r  = 16*wid + (lane & 15);
        int cg = (lane >> 4) & 1;
        #pragma unroll
        for (int kt = 0; kt < 4; kt++)
            LDSM4(qf[kt], sb + r*PITCH + (kt*16 + cg*8)*2);
    }
    __syncthreads();   // Q reads done before cp.async overwrites buf0

    // ---- prologue: async tiles 0,1 ----
    load_tile_async(sb, 0, kg, vg, 0,   tid); CP_COMMIT();
    load_tile_async(sb, 1, kg, vg, 128, tid); CP_COMMIT();
    CP_WAIT1();        // tile 0 complete (this thread)
    __syncthreads();   // tile 0 visible CTA-wide

    float oacc[8][4];
    #pragma unroll
    for (int j = 0; j < 8; j++)
        #pragma unroll
        for (int c = 0; c < 4; c++) oacc[j][c] = 0.f;
    float l0 = 0.f, l1 = 0.f;

    const uint32_t klane = ((lane & 7) + ((lane >> 4) & 1)*8)*PITCH + ((lane >> 3) & 1)*16;
    const uint32_t vlane = 18432 + ((lane & 7) + ((lane >> 3) & 1)*8)*PITCH + ((lane >> 4) & 1)*16;

    for (int t = 0; t < 32; t++) {
        // issue tile t+2 into buf (t+2)%3: last read at compute(t-1),
        // ordered before this write by the barrier that ended iter t-1.
        if (t < 30) {
            load_tile_async(sb, (t + 2) % 3, kg, vg, (t + 2) << 7, tid);
            CP_COMMIT();
        }

        const uint32_t base = sb + (t % 3)*TILEB;

        #pragma unroll
        for (int h = 0; h < 2; h++) {
            const uint32_t kb = base + h*(64*PITCH) + klane;
            const uint32_t vb = base + h*(64*PITCH) + vlane;

            // ---- S = Q K^T ----
            float sacc[8][4];
            #pragma unroll
            for (int j = 0; j < 8; j++)
                #pragma unroll
                for (int c = 0; c < 4; c++) sacc[j][c] = 0.f;

            #pragma unroll
            for (int ks = 0; ks < 4; ks++) {
                uint32_t kf0[4], kf1[4], kf2[4], kf3[4];
                LDSM4(kf0, kb + 0*(16*PITCH) + ks*32);
                LDSM4(kf1, kb + 1*(16*PITCH) + ks*32);
                LDSM4(kf2, kb + 2*(16*PITCH) + ks*32);
                LDSM4(kf3, kb + 3*(16*PITCH) + ks*32);
                MMA16816(sacc[0], qf[ks], kf0[0], kf0[1]);
                MMA16816(sacc[1], qf[ks], kf0[2], kf0[3]);
                MMA16816(sacc[2], qf[ks], kf1[0], kf1[1]);
                MMA16816(sacc[3], qf[ks], kf1[2], kf1[3]);
                MMA16816(sacc[4], qf[ks], kf2[0], kf2[1]);
                MMA16816(sacc[5], qf[ks], kf2[2], kf2[3]);
                MMA16816(sacc[6], qf[ks], kf3[0], kf3[1]);
                MMA16816(sacc[7], qf[ks], kf3[2], kf3[3]);
            }

            // ---- per 16-key chunk: f32 exp2 + row sums + pack + O-MMAs ----
            #pragma unroll
            for (int ks = 0; ks < 4; ks++) {
                float* s0 = sacc[2*ks];
                float* s1 = sacc[2*ks + 1];
                s0[0] = fexp2(s0[0]); s0[1] = fexp2(s0[1]);
                s0[2] = fexp2(s0[2]); s0[3] = fexp2(s0[3]);
                s1[0] = fexp2(s1[0]); s1[1] = fexp2(s1[1]);
                s1[2] = fexp2(s1[2]); s1[3] = fexp2(s1[3]);
                l0 += s0[0] + s0[1] + s1[0] + s1[1];
                l1 += s0[2] + s0[3] + s1[2] + s1[3];

                uint32_t ph[4];
                __half2 h0 = __floats2half2_rn(s0[0], s0[1]);
                __half2 h1 = __floats2half2_rn(s0[2], s0[3]);
                __half2 h2 = __floats2half2_rn(s1[0], s1[1]);
                __half2 h3 = __floats2half2_rn(s1[2], s1[3]);
                ph[0] = *reinterpret_cast<uint32_t*>(&h0);
                ph[1] = *reinterpret_cast<uint32_t*>(&h1);
                ph[2] = *reinterpret_cast<uint32_t*>(&h2);
                ph[3] = *reinterpret_cast<uint32_t*>(&h3);

                #pragma unroll
                for (int cg = 0; cg < 4; cg++) {
                    uint32_t vf[4];
                    LDSM4T(vf, vb + ks*(16*PITCH) + cg*32);
                    MMA16816(oacc[2*cg],   ph, vf[0], vf[1]);
                    MMA16816(oacc[2*cg+1], ph, vf[2], vf[3]);
                }
            }
        }

        // tile t+1 complete for this thread, then CTA-visible
        if (t < 30) CP_WAIT1(); else CP_WAIT0();
        __syncthreads();
    }

    // ---- epilogue: normalize, mix GEMM + ReLU, 2x2 pool, store ----
    l0 += __shfl_xor_sync(0xffffffffu, l0, 1);
    l0 += __shfl_xor_sync(0xffffffffu, l0, 2);
    l1 += __shfl_xor_sync(0xffffffffu, l1, 1);
    l1 += __shfl_xor_sync(0xffffffffu, l1, 2);
    float inv0 = 1.f / l0, inv1 = 1.f / l1;

    float* sm_o = (float*)smem;               // o^T [64 c][132] = 33792 B
    float* wmT  = (float*)(smem + 36864);     // wmT[c][d], 16384 B
    {
        int r  = 16*wid + (lane >> 2);
        int c0 = 2*(lane & 3);
        #pragma unroll
        for (int j = 0; j < 8; j++) {
            sm_o[(8*j + c0    )*132 + r]     = oacc[j][0]*inv0;
            sm_o[(8*j + c0 + 1)*132 + r]     = oacc[j][1]*inv0;
            sm_o[(8*j + c0    )*132 + r + 8] = oacc[j][2]*inv1;
            sm_o[(8*j + c0 + 1)*132 + r + 8] = oacc[j][3]*inv1;
        }
    }
    // load wmT while sm_o writes settle (disjoint smem regions)
    #pragma unroll
    for (int k = 0; k < 16; k++) {
        int e = tid + 256*k;
        wmT[(e & 63)*64 + (e >> 6)] = wm[e];
    }
    __syncthreads();

    // mix GEMM: mixed[t][d] = relu(bm[d] + sum_c o[t][c]*wm[d][c])
    int tx = tid & 15, ty = tid >> 4;
    float4 bmv = ((const float4*)bm)[tx];
    float acc[8][4];
    #pragma unroll
    for (int ii = 0; ii < 8; ii++) {
        acc[ii][0] = bmv.x; acc[ii][1] = bmv.y; acc[ii][2] = bmv.z; acc[ii][3] = bmv.w;
    }
    #pragma unroll 8
    for (int c = 0; c < 64; c++) {
        float4 wv = *(const float4*)(wmT + c*64 + 4*tx);
        float4 o0 = *(const float4*)(sm_o + c*132 + 8*ty);
        float4 o1 = *(const float4*)(sm_o + c*132 + 8*ty + 4);
        float ov[8] = {o0.x,o0.y,o0.z,o0.w,o1.x,o1.y,o1.z,o1.w};
        #pragma unroll
        for (int ii = 0; ii < 8; ii++) {
            acc[ii][0] = fmaf(ov[ii], wv.x, acc[ii][0]);
            acc[ii][1] = fmaf(ov[ii], wv.y, acc[ii][1]);
            acc[ii][2] = fmaf(ov[ii], wv.z, acc[ii][2]);
            acc[ii][3] = fmaf(ov[ii], wv.w, acc[ii][3]);
        }
    }
    __syncthreads();   // done reading sm_o

    float* sm_mx = (float*)smem;    // mixed [128 t][68] = 34816 B (< wmT offset)
    #pragma unroll
    for (int ii = 0; ii < 8; ii++) {
        float4 mv = make_float4(fmaxf(acc[ii][0], 0.f), fmaxf(acc[ii][1], 0.f),
                                fmaxf(acc[ii][2], 0.f), fmaxf(acc[ii][3], 0.f));
        *(float4*)(sm_mx + (8*ty + ii)*68 + 4*tx) = mv;
    }
    __syncthreads();

    float* ob = out + (size_t)b*C_*1024 + (size_t)it*32;
    #pragma unroll
    for (int k = 0; k < 8; k++) {
        int e = tid + 256*k;
        int j = e & 31, d = e >> 5;
        float v = sm_mx[(2*j)*68 + d] + sm_mx[(2*j + 1)*68 + d]
                + sm_mx[(64 + 2*j)*68 + d] + sm_mx[(64 + 2*j + 1)*68 + d];
        ob[(size_t)d*1024 + j] = 0.25f * v;
    }
}

extern "C" void kernel_launch(void* const* d_in, const int* in_sizes, int n_in,
                              void* d_out, int out_size)
{
    const float* x  = (const float*)d_in[0];
    const float* wq = (const float*)d_in[1];
    const float* bq = (const float*)d_in[2];
    const float* wk = (const float*)d_in[3];
    const float* bk = (const float*)d_in[4];
    const float* wv = (const float*)d_in[5];
    const float* bv = (const float*)d_in[6];
    const float* wm = (const float*)d_in[7];
    const float* bm = (const float*)d_in[8];
    float* out = (float*)d_out;

    cudaFuncSetAttribute(qkv_kernel,  cudaFuncAttributeMaxDynamicSharedMemorySize, QKV_SMEM);
    cudaFuncSetAttribute(attn_kernel, cudaFuncAttributeMaxDynamicSharedMemorySize, ATTN_SMEM);

    qkv_kernel<<<512, 256, QKV_SMEM>>>(x, wq, bq, wk, bk, wv, bv);
    attn_kernel<<<256, 256, ATTN_SMEM>>>(wm, bm, out);
}

// round 13
// speedup vs baseline: 1.2180x; 1.1231x over previous
#include <cuda_runtime.h>
#include <cuda_fp16.h>
#include <cstdint>

#define B_  8
#define C_  64
#define HW_ 4096

// ---------------- scratch globals (no allocation) ----------------
__device__ __half g_q[(size_t)B_*HW_*C_];   // [b][n][c]  (scaled by log2e/8)
__device__ __half g_k[(size_t)B_*HW_*C_];   // [b][n][c]
__device__ __half g_v[(size_t)B_*HW_*C_];   // [b][n][c]

__device__ __forceinline__ uint32_t smem_u32(const void* p) {
    uint32_t a;
    asm("{ .reg .u64 t; cvta.to.shared.u64 t, %1; cvt.u32.u64 %0, t; }" : "=r"(a) : "l"(p));
    return a;
}

#define MMA16816(c, a, b0, b1)                                                  \
    asm volatile("mma.sync.aligned.m16n8k16.row.col.f32.f16.f16.f32 "           \
        "{%0,%1,%2,%3}, {%4,%5,%6,%7}, {%8,%9}, {%0,%1,%2,%3};"                 \
        : "+f"((c)[0]), "+f"((c)[1]), "+f"((c)[2]), "+f"((c)[3])                \
        : "r"((a)[0]), "r"((a)[1]), "r"((a)[2]), "r"((a)[3]), "r"(b0), "r"(b1))

#define LDSM4(r, a)                                                             \
    asm volatile("ldmatrix.sync.aligned.m8n8.x4.shared.b16 {%0,%1,%2,%3}, [%4];"\
        : "=r"((r)[0]), "=r"((r)[1]), "=r"((r)[2]), "=r"((r)[3]) : "r"(a))

#define LDSM4T(r, a)                                                            \
    asm volatile("ldmatrix.sync.aligned.m8n8.x4.trans.shared.b16 {%0,%1,%2,%3}, [%4];"\
        : "=r"((r)[0]), "=r"((r)[1]), "=r"((r)[2]), "=r"((r)[3]) : "r"(a))

// hardware exp2 (MUFU.EX2 f32)
__device__ __forceinline__ float fexp2(float x) {
    float y;
    asm("ex2.approx.f32 %0, %1;" : "=f"(y) : "f"(x));
    return y;
}

#define PITCH 144   // bytes per 64-half row (8 halves padding), shared by both kernels

// ---------------------------------------------------------------------------
// QKV projection via HMMA. One CTA per (b, 128-token tile). x and w converted
// to fp16 in smem; 3 GEMMs [128x64] = X[128x64] @ W^T; bias + scale epilogue;
// outputs fp16 [b][n][c]. Q pre-scaled by log2(e)/sqrt(C).
// ---------------------------------------------------------------------------
__global__ __launch_bounds__(256) void qkv_kernel(
    const float* __restrict__ x,
    const float* __restrict__ wq, const float* __restrict__ bq,
    const float* __restrict__ wk, const float* __restrict__ bk,
    const float* __restrict__ wv, const float* __restrict__ bv)
{
    __shared__ __align__(16) char xs[128*PITCH];      // x^T fp16 [token][c]
    __shared__ __align__(16) char ws[3*64*PITCH];     // w fp16 [m][d][c]
    __shared__ float bsh[3*64];

    int tid = threadIdx.x, wid = tid >> 5, lane = tid & 31;
    int b  = blockIdx.x >> 5;
    int n0 = (blockIdx.x & 31) << 7;
    const float* xb = x + (size_t)b*C_*HW_;

    // x tile: read coalesced along n, store transposed fp16 [token][c]
    #pragma unroll
    for (int k = 0; k < 8; k++) {
        int e = tid + 256*k;              // 2048 float4s = 64c x 32 token-quads
        int c = e >> 5, t4 = (e & 31) << 2;
        float4 v = *(const float4*)(xb + (size_t)c*HW_ + n0 + t4);
        *(__half*)(xs + (t4    )*PITCH + c*2) = __float2half_rn(v.x);
        *(__half*)(xs + (t4 + 1)*PITCH + c*2) = __float2half_rn(v.y);
        *(__half*)(xs + (t4 + 2)*PITCH + c*2) = __float2half_rn(v.z);
        *(__half*)(xs + (t4 + 3)*PITCH + c*2) = __float2half_rn(v.w);
    }
    // weights: [d][c] rows, fp16
    const float* wptr[3] = {wq, wk, wv};
    #pragma unroll
    for (int m = 0; m < 3; m++) {
        char* wsm = ws + m*64*PITCH;
        #pragma unroll
        for (int k = 0; k < 4; k++) {
            int e = tid + 256*k;          // 1024 float4s = 64d x 16 c-quads
            int d = e >> 4, c4 = (e & 15) << 2;
            float4 v = *(const float4*)(wptr[m] + (size_t)d*C_ + c4);
            __half2 h01 = __floats2half2_rn(v.x, v.y);
            __half2 h23 = __floats2half2_rn(v.z, v.w);
            *(__half2*)(wsm + d*PITCH + c4*2)     = h01;
            *(__half2*)(wsm + d*PITCH + c4*2 + 4) = h23;
        }
    }
    if (tid < 192) {
        bsh[tid] = (tid < 64) ? bq[tid] : (tid < 128) ? bk[tid - 64] : bv[tid - 128];
    }
    __syncthreads();

    const uint32_t sxs = smem_u32(xs);
    const uint32_t sws = smem_u32(ws);

    // A fragments: this warp's 16 tokens, all 64 channels
    uint32_t af[4][4];
    {
        int r  = 16*wid + (lane & 15);
        int cg = (lane >> 4) & 1;
        #pragma unroll
        for (int ks = 0; ks < 4; ks++)
            LDSM4(af[ks], sxs + r*PITCH + (ks*16 + cg*8)*2);
    }

    const uint32_t blane = ((lane & 7) + ((lane >> 4) & 1)*8)*PITCH + ((lane >> 3) & 1)*16;
    __half* outp[3] = {g_q + (size_t)b*HW_*C_, g_k + (size_t)b*HW_*C_, g_v + (size_t)b*HW_*C_};
    const float scl[3] = {0.18033688011112043f, 1.0f, 1.0f};   // log2(e)/8 on Q

    int r = lane >> 2, c0 = 2*(lane & 3);
    #pragma unroll
    for (int m = 0; m < 3; m++) {
        float acc[8][4];
        #pragma unroll
        for (int j = 0; j < 8; j++)
            #pragma unroll
            for (int c = 0; c < 4; c++) acc[j][c] = 0.f;

        const uint32_t wb = sws + m*64*PITCH + blane;
        #pragma unroll
        for (int ks = 0; ks < 4; ks++) {
            uint32_t f0[4], f1[4], f2[4], f3[4];
            LDSM4(f0, wb + 0*(16*PITCH) + ks*32);
            LDSM4(f1, wb + 1*(16*PITCH) + ks*32);
            LDSM4(f2, wb + 2*(16*PITCH) + ks*32);
            LDSM4(f3, wb + 3*(16*PITCH) + ks*32);
            MMA16816(acc[0], af[ks], f0[0], f0[1]);
            MMA16816(acc[1], af[ks], f0[2], f0[3]);
            MMA16816(acc[2], af[ks], f1[0], f1[1]);
            MMA16816(acc[3], af[ks], f1[2], f1[3]);
            MMA16816(acc[4], af[ks], f2[0], f2[1]);
            MMA16816(acc[5], af[ks], f2[2], f2[3]);
            MMA16816(acc[6], af[ks], f3[0], f3[1]);
            MMA16816(acc[7], af[ks], f3[2], f3[3]);
        }

        // epilogue: bias + scale, fp16 store
        float sc = scl[m];
        __half* og = outp[m] + (size_t)(n0 + 16*wid + r)*C_;
        #pragma unroll
        for (int j = 0; j < 8; j++) {
            float bz0 = bsh[m*64 + 8*j + c0], bz1 = bsh[m*64 + 8*j + c0 + 1];
            __half2 lo = __floats2half2_rn((acc[j][0] + bz0)*sc, (acc[j][1] + bz1)*sc);
            __half2 hi = __floats2half2_rn((acc[j][2] + bz0)*sc, (acc[j][3] + bz1)*sc);
            *(__half2*)(og + 8*j + c0)        = lo;
            *(__half2*)(og + 8*C_ + 8*j + c0) = hi;
        }
    }
}

// ---------------------------------------------------------------------------
// Fused flash attention (R6 exactly — best measured): HMMA, register-staged
// double-buffered K/V, interleaved f32 MUFU softmax, mix/ReLU/2x2-pool epi.
// ---------------------------------------------------------------------------
#define KVBUF 18432
#define SM_WMT 36864
#define ATTN_SMEM (36864 + 16384)

__global__ __launch_bounds__(256, 2) void attn_kernel(
    const float* __restrict__ wm, const float* __restrict__ bm,
    float* __restrict__ out)
{
    extern __shared__ __align__(16) char smem[];
    const uint32_t sb = smem_u32(smem);
    float* wmT = (float*)(smem + SM_WMT);

    int tid = threadIdx.x, wid = tid >> 5, lane = tid & 31;
    int b  = blockIdx.x >> 5;
    int it = blockIdx.x & 31;
    int n0 = it << 7;

    const __half* kg = g_k + (size_t)b*HW_*C_;
    const __half* vg = g_v + (size_t)b*HW_*C_;

    #pragma unroll
    for (int k = 0; k < 16; k++) {
        int e = tid + 256*k;
        wmT[(e & 63)*64 + (e >> 6)] = wm[e];
    }

    const int e0 = tid, e1 = tid + 256;
    const int so0 = (e0 >> 3)*PITCH + (e0 & 7)*16;
    const int so1 = (e1 >> 3)*PITCH + (e1 & 7)*16;

    {
        const float4* q4 = (const float4*)(g_q + ((size_t)b*HW_ + n0)*C_);
        #pragma unroll
        for (int k = 0; k < 4; k++) {
            int e = tid + 256*k;
            *(float4*)(smem + (e >> 3)*PITCH + (e & 7)*16) = q4[e];
        }
    }
    __syncthreads();

    uint32_t qf[4][4];
    {
        int r  = 16*wid + (lane & 15);
        int cg = (lane >> 4) & 1;
        #pragma unroll
        for (int kt = 0; kt < 4; kt++)
            LDSM4(qf[kt], sb + r*PITCH + (kt*16 + cg*8)*2);
    }

    float4 rk0, rk1, rv0, rv1;
    {
        const float4* k4 = (const float4*)kg;
        const float4* v4 = (const float4*)vg;
        rk0 = k4[e0]; rk1 = k4[e1]; rv0 = v4[e0]; rv1 = v4[e1];
    }
    __syncthreads();
    *(float4*)(smem + so0) = rk0;        *(float4*)(smem + so1) = rk1;
    *(float4*)(smem + 9216 + so0) = rv0; *(float4*)(smem + 9216 + so1) = rv1;
    {
        const float4* k4 = (const float4*)(kg + (size_t)64*C_);
        const float4* v4 = (const float4*)(vg + (size_t)64*C_);
        rk0 = k4[e0]; rk1 = k4[e1]; rv0 = v4[e0]; rv1 = v4[e1];
    }

    float oacc[8][4];
    #pragma unroll
    for (int j = 0; j < 8; j++)
        #pragma unroll
        for (int c = 0; c < 4; c++) oacc[j][c] = 0.f;
    float l0 = 0.f, l1 = 0.f;

    const uint32_t klane = ((lane & 7) + ((lane >> 4) & 1)*8)*PITCH + ((lane >> 3) & 1)*16;
    const uint32_t vlane = 9216 + ((lane & 7) + ((lane >> 3) & 1)*8)*PITCH + ((lane >> 4) & 1)*16;

    for (int t = 0; t < 64; t++) {
        __syncthreads();
        uint32_t cur = sb + (t & 1)*KVBUF;

        if (t < 63) {
            char* nb = smem + ((t + 1) & 1)*KVBUF;
            *(float4*)(nb + so0) = rk0;        *(float4*)(nb + so1) = rk1;
            *(float4*)(nb + 9216 + so0) = rv0; *(float4*)(nb + 9216 + so1) = rv1;
            if (t < 62) {
                const float4* k4 = (const float4*)(kg + (size_t)(t + 2)*64*C_);
                const float4* v4 = (const float4*)(vg + (size_t)(t + 2)*64*C_);
                rk0 = k4[e0]; rk1 = k4[e1]; rv0 = v4[e0]; rv1 = v4[e1];
            }
        }

        float sacc[8][4];
        #pragma unroll
        for (int j = 0; j < 8; j++)
            #pragma unroll
            for (int c = 0; c < 4; c++) sacc[j][c] = 0.f;

        const uint32_t kb = cur + klane;
        #pragma unroll
        for (int ks = 0; ks < 4; ks++) {
            uint32_t kf0[4], kf1[4], kf2[4], kf3[4];
            LDSM4(kf0, kb + 0*(16*PITCH) + ks*32);
            LDSM4(kf1, kb + 1*(16*PITCH) + ks*32);
            LDSM4(kf2, kb + 2*(16*PITCH) + ks*32);
            LDSM4(kf3, kb + 3*(16*PITCH) + ks*32);
            MMA16816(sacc[0], qf[ks], kf0[0], kf0[1]);
            MMA16816(sacc[1], qf[ks], kf0[2], kf0[3]);
            MMA16816(sacc[2], qf[ks], kf1[0], kf1[1]);
            MMA16816(sacc[3], qf[ks], kf1[2], kf1[3]);
            MMA16816(sacc[4], qf[ks], kf2[0], kf2[1]);
            MMA16816(sacc[5], qf[ks], kf2[2], kf2[3]);
            MMA16816(sacc[6], qf[ks], kf3[0], kf3[1]);
            MMA16816(sacc[7], qf[ks], kf3[2], kf3[3]);
        }

        const uint32_t vb = cur + vlane;
        #pragma unroll
        for (int ks = 0; ks < 4; ks++) {
            float* s0 = sacc[2*ks];
            float* s1 = sacc[2*ks + 1];
            s0[0] = fexp2(s0[0]); s0[1] = fexp2(s0[1]);
            s0[2] = fexp2(s0[2]); s0[3] = fexp2(s0[3]);
            s1[0] = fexp2(s1[0]); s1[1] = fexp2(s1[1]);
            s1[2] = fexp2(s1[2]); s1[3] = fexp2(s1[3]);
            l0 += s0[0] + s0[1] + s1[0] + s1[1];
            l1 += s0[2] + s0[3] + s1[2] + s1[3];

            uint32_t ph[4];
            __half2 h0 = __floats2half2_rn(s0[0], s0[1]);
            __half2 h1 = __floats2half2_rn(s0[2], s0[3]);
            __half2 h2 = __floats2half2_rn(s1[0], s1[1]);
            __half2 h3 = __floats2half2_rn(s1[2], s1[3]);
            ph[0] = *reinterpret_cast<uint32_t*>(&h0);
            ph[1] = *reinterpret_cast<uint32_t*>(&h1);
            ph[2] = *reinterpret_cast<uint32_t*>(&h2);
            ph[3] = *reinterpret_cast<uint32_t*>(&h3);

            #pragma unroll
            for (int cg = 0; cg < 4; cg++) {
                uint32_t vf[4];
                LDSM4T(vf, vb + ks*(16*PITCH) + cg*32);
                MMA16816(oacc[2*cg],   ph, vf[0], vf[1]);
                MMA16816(oacc[2*cg+1], ph, vf[2], vf[3]);
            }
        }
    }

    // ---- epilogue: normalize, mix GEMM + ReLU, 2x2 pool, store ----
    l0 += __shfl_xor_sync(0xffffffffu, l0, 1);
    l0 += __shfl_xor_sync(0xffffffffu, l0, 2);
    l1 += __shfl_xor_sync(0xffffffffu, l1, 1);
    l1 += __shfl_xor_sync(0xffffffffu, l1, 2);
    float inv0 = 1.f / l0, inv1 = 1.f / l1;

    __syncthreads();
    float* sm_o = (float*)smem;     // o^T [64 c][132]
    {
        int r  = 16*wid + (lane >> 2);
        int c0 = 2*(lane & 3);
        #pragma unroll
        for (int j = 0; j < 8; j++) {
            sm_o[(8*j + c0    )*132 + r]     = oacc[j][0]*inv0;
            sm_o[(8*j + c0 + 1)*132 + r]     = oacc[j][1]*inv0;
            sm_o[(8*j + c0    )*132 + r + 8] = oacc[j][2]*inv1;
            sm_o[(8*j + c0 + 1)*132 + r + 8] = oacc[j][3]*inv1;
        }
    }
    __syncthreads();

    int tx = tid & 15, ty = tid >> 4;
    float4 bmv = ((const float4*)bm)[tx];
    float acc[8][4];
    #pragma unroll
    for (int ii = 0; ii < 8; ii++) {
        acc[ii][0] = bmv.x; acc[ii][1] = bmv.y; acc[ii][2] = bmv.z; acc[ii][3] = bmv.w;
    }
    #pragma unroll 8
    for (int c = 0; c < 64; c++) {
        float4 wv = *(const float4*)(wmT + c*64 + 4*tx);
        float4 o0 = *(const float4*)(sm_o + c*132 + 8*ty);
        float4 o1 = *(const float4*)(sm_o + c*132 + 8*ty + 4);
        float ov[8] = {o0.x,o0.y,o0.z,o0.w,o1.x,o1.y,o1.z,o1.w};
        #pragma unroll
        for (int ii = 0; ii < 8; ii++) {
            acc[ii][0] = fmaf(ov[ii], wv.x, acc[ii][0]);
            acc[ii][1] = fmaf(ov[ii], wv.y, acc[ii][1]);
            acc[ii][2] = fmaf(ov[ii], wv.z, acc[ii][2]);
            acc[ii][3] = fmaf(ov[ii], wv.w, acc[ii][3]);
        }
    }
    __syncthreads();

    float* sm_mx = (float*)smem;    // mixed [128 t][68]
    #pragma unroll
    for (int ii = 0; ii < 8; ii++) {
        float4 mv = make_float4(fmaxf(acc[ii][0], 0.f), fmaxf(acc[ii][1], 0.f),
                                fmaxf(acc[ii][2], 0.f), fmaxf(acc[ii][3], 0.f));
        *(float4*)(sm_mx + (8*ty + ii)*68 + 4*tx) = mv;
    }
    __syncthreads();

    float* ob = out + (size_t)b*C_*1024 + (size_t)it*32;
    #pragma unroll
    for (int k = 0; k < 8; k++) {
        int e = tid + 256*k;
        int j = e & 31, d = e >> 5;
        float v = sm_mx[(2*j)*68 + d] + sm_mx[(2*j + 1)*68 + d]
                + sm_mx[(64 + 2*j)*68 + d] + sm_mx[(64 + 2*j + 1)*68 + d];
        ob[(size_t)d*1024 + j] = 0.25f * v;
    }
}

extern "C" void kernel_launch(void* const* d_in, const int* in_sizes, int n_in,
                              void* d_out, int out_size)
{
    const float* x  = (const float*)d_in[0];
    const float* wq = (const float*)d_in[1];
    const float* bq = (const float*)d_in[2];
    const float* wk = (const float*)d_in[3];
    const float* bk = (const float*)d_in[4];
    const float* wv = (const float*)d_in[5];
    const float* bv = (const float*)d_in[6];
    const float* wm = (const float*)d_in[7];
    const float* bm = (const float*)d_in[8];
    float* out = (float*)d_out;

    cudaFuncSetAttribute(attn_kernel, cudaFuncAttributeMaxDynamicSharedMemorySize, ATTN_SMEM);

    qkv_kernel<<<256, 256>>>(x, wq, bq, wk, bk, wv, bv);
    attn_kernel<<<256, 256, ATTN_SMEM>>>(wm, bm, out);
}